// round 7
// baseline (speedup 1.0000x reference)
#include <cuda_runtime.h>
#include <math.h>

#define N_VOX 196608
#define CDIM 192
#define SETS 4096
#define SETL 48
#define NHEAD 8
#define HDIM 24
#define FDIM 384

// ---------------- scratch (static __device__, allocation-free) ----------------
__device__ float g_qk  [(size_t)N_VOX * 2 * CDIM];  // Q | K packed, 384 per row
__device__ float g_v   [(size_t)N_VOX * CDIM];
__device__ float g_ctx [(size_t)N_VOX * CDIM];
__device__ float g_src2[(size_t)N_VOX * CDIM];
__device__ float g_x1  [(size_t)N_VOX * CDIM];
__device__ float g_h   [(size_t)N_VOX * FDIM];
__device__ float g_ffn [(size_t)N_VOX * CDIM];

// ---------------- generic fp32 GEMM: C = A(N x K) @ W(M x K)^T + bias --------
// BM=128 rows, BN=64 cols, BK=16, 128 threads, 8x8 micro-tile per thread.
template<bool ADD2, bool RELU>
__global__ __launch_bounds__(128)
void gemm_kernel(const float* __restrict__ A, const float* __restrict__ A2,
                 const float* __restrict__ W, const float* __restrict__ bias,
                 float* __restrict__ Cout, int K, int M) {
  __shared__ __align__(16) float As[128][17];
  __shared__ __align__(16) float Bs[16][64];
  const int c0 = blockIdx.x * 64;    // col block (fast dim -> L2 reuse of A rows)
  const int r0 = blockIdx.y * 128;   // row block
  const int tid = threadIdx.x;
  const int cx = tid & 7;            // 0..7  -> 8 output cols
  const int cy = tid >> 3;           // 0..15 -> 8 output rows

  float acc[8][8];
#pragma unroll
  for (int i = 0; i < 8; i++)
#pragma unroll
    for (int j = 0; j < 8; j++) acc[i][j] = 0.f;

  for (int k0 = 0; k0 < K; k0 += 16) {
    // load A tile: 128x16 = 512 float4, 4 per thread (coalesced 64B runs)
#pragma unroll
    for (int t = 0; t < 4; t++) {
      int f = t * 128 + tid;
      int row = f >> 2, cq = f & 3;
      float4 av = *(const float4*)(A + (size_t)(r0 + row) * K + k0 + cq * 4);
      if (ADD2) {
        float4 bv = *(const float4*)(A2 + (size_t)(r0 + row) * K + k0 + cq * 4);
        av.x += bv.x; av.y += bv.y; av.z += bv.z; av.w += bv.w;
      }
      As[row][cq * 4 + 0] = av.x; As[row][cq * 4 + 1] = av.y;
      As[row][cq * 4 + 2] = av.z; As[row][cq * 4 + 3] = av.w;
    }
    // load W tile (transposed into Bs[k][m]): 64x16 = 256 float4, 2 per thread
#pragma unroll
    for (int t = 0; t < 2; t++) {
      int f = t * 128 + tid;
      int m = f >> 2, kq = f & 3;
      float4 wv = *(const float4*)(W + (size_t)(c0 + m) * K + k0 + kq * 4);
      Bs[kq * 4 + 0][m] = wv.x; Bs[kq * 4 + 1][m] = wv.y;
      Bs[kq * 4 + 2][m] = wv.z; Bs[kq * 4 + 3][m] = wv.w;
    }
    __syncthreads();
#pragma unroll
    for (int kk = 0; kk < 16; kk++) {
      float a[8];
#pragma unroll
      for (int ii = 0; ii < 8; ii++) a[ii] = As[cy * 8 + ii][kk];
      float4 bA = *(const float4*)&Bs[kk][cx * 8];
      float4 bB = *(const float4*)&Bs[kk][cx * 8 + 4];
      float b[8] = {bA.x, bA.y, bA.z, bA.w, bB.x, bB.y, bB.z, bB.w};
#pragma unroll
      for (int ii = 0; ii < 8; ii++)
#pragma unroll
        for (int jj = 0; jj < 8; jj++) acc[ii][jj] += a[ii] * b[jj];
    }
    __syncthreads();
  }

  float bb[8];
#pragma unroll
  for (int j = 0; j < 8; j++) bb[j] = bias[c0 + cx * 8 + j];
#pragma unroll
  for (int ii = 0; ii < 8; ii++) {
    size_t base = (size_t)(r0 + cy * 8 + ii) * M + c0 + cx * 8;
    float o[8];
#pragma unroll
    for (int j = 0; j < 8; j++) {
      o[j] = acc[ii][j] + bb[j];
      if (RELU) o[j] = fmaxf(o[j], 0.f);
    }
    *(float4*)(Cout + base)     = make_float4(o[0], o[1], o[2], o[3]);
    *(float4*)(Cout + base + 4) = make_float4(o[4], o[5], o[6], o[7]);
  }
}

// ---------------- per-set attention: gather -> softmax(QK^T)V -> scatter -----
__global__ __launch_bounds__(256)
void attn_kernel(const float* __restrict__ qk, const float* __restrict__ v,
                 const int* __restrict__ inds, const unsigned char* __restrict__ mask,
                 float* __restrict__ ctx_out) {
  extern __shared__ __align__(16) float sm[];
  float* sq = sm;                       // 48*192 (later reused for ctx output)
  float* sk = sq + SETL * CDIM;         // 48*192
  float* sv = sk + SETL * CDIM;         // 48*192
  float* ss = sv + SETL * CDIM;         // 8*48*48 scores
  __shared__ int   sind[SETL];
  __shared__ float smask[SETL];

  const int set = blockIdx.x;
  const int tid = threadIdx.x;
  if (tid < SETL) {
    sind[tid]  = inds[set * SETL + tid];
    smask[tid] = mask[set * SETL + tid] ? -1e9f : 0.f;
  }
  __syncthreads();

  // gather Q,K (packed 384/row) and V (192/row), float4 coalesced
  for (int e = tid; e < SETL * 96; e += 256) {
    int l = e / 96, c4 = e % 96;
    float4 val = *(const float4*)(qk + (size_t)sind[l] * 384 + c4 * 4);
    if (c4 < 48) *(float4*)(sq + l * CDIM + c4 * 4) = val;
    else         *(float4*)(sk + l * CDIM + (c4 - 48) * 4) = val;
  }
  for (int e = tid; e < SETL * 48; e += 256) {
    int l = e / 48, c4 = e % 48;
    *(float4*)(sv + l * CDIM + c4 * 4) =
        *(const float4*)(v + (size_t)sind[l] * CDIM + c4 * 4);
  }
  __syncthreads();

  // scores: per head 48x48, 4x4 register tiles -> 8*12*12 = 1152 tiles
  const float scale = 0.2041241452319315f;  // 1/sqrt(24)
  for (int t = tid; t < 1152; t += 256) {
    int h = t / 144, rem = t % 144;
    int i0 = (rem / 12) * 4, j0 = (rem % 12) * 4;
    float acc[4][4] = {};
#pragma unroll
    for (int d4 = 0; d4 < 6; d4++) {
      float4 qv[4], kv[4];
#pragma unroll
      for (int ii = 0; ii < 4; ii++)
        qv[ii] = *(const float4*)(sq + (i0 + ii) * CDIM + h * HDIM + d4 * 4);
#pragma unroll
      for (int jj = 0; jj < 4; jj++)
        kv[jj] = *(const float4*)(sk + (j0 + jj) * CDIM + h * HDIM + d4 * 4);
#pragma unroll
      for (int ii = 0; ii < 4; ii++)
#pragma unroll
        for (int jj = 0; jj < 4; jj++)
          acc[ii][jj] += qv[ii].x * kv[jj].x + qv[ii].y * kv[jj].y +
                         qv[ii].z * kv[jj].z + qv[ii].w * kv[jj].w;
    }
#pragma unroll
    for (int ii = 0; ii < 4; ii++)
#pragma unroll
      for (int jj = 0; jj < 4; jj++)
        ss[h * 2304 + (i0 + ii) * 48 + j0 + jj] = acc[ii][jj] * scale + smask[j0 + jj];
  }
  __syncthreads();

  // softmax over last dim, one thread per (h, i) row: 384 rows
  for (int r = tid; r < 384; r += 256) {
    float* row = ss + r * 48;
    float mx = row[0];
#pragma unroll
    for (int j = 1; j < 48; j++) mx = fmaxf(mx, row[j]);
    float sum = 0.f;
#pragma unroll
    for (int j = 0; j < 48; j++) { float e = expf(row[j] - mx); row[j] = e; sum += e; }
    float inv = 1.f / sum;
#pragma unroll
    for (int j = 0; j < 48; j++) row[j] *= inv;
  }
  __syncthreads();

  // ctx = P @ V per head, 4x4 tiles over (i, d): 8*12*6 = 576 tiles; write into sq
  for (int t = tid; t < 576; t += 256) {
    int h = t / 72, rem = t % 72;
    int i0 = (rem / 6) * 4, d0 = (rem % 6) * 4;
    float acc[4][4] = {};
    for (int j = 0; j < 48; j++) {
      float4 vv = *(const float4*)(sv + j * CDIM + h * HDIM + d0);
      float p0 = ss[h * 2304 + (i0 + 0) * 48 + j];
      float p1 = ss[h * 2304 + (i0 + 1) * 48 + j];
      float p2 = ss[h * 2304 + (i0 + 2) * 48 + j];
      float p3 = ss[h * 2304 + (i0 + 3) * 48 + j];
      acc[0][0] += p0 * vv.x; acc[0][1] += p0 * vv.y; acc[0][2] += p0 * vv.z; acc[0][3] += p0 * vv.w;
      acc[1][0] += p1 * vv.x; acc[1][1] += p1 * vv.y; acc[1][2] += p1 * vv.z; acc[1][3] += p1 * vv.w;
      acc[2][0] += p2 * vv.x; acc[2][1] += p2 * vv.y; acc[2][2] += p2 * vv.z; acc[2][3] += p2 * vv.w;
      acc[3][0] += p3 * vv.x; acc[3][1] += p3 * vv.y; acc[3][2] += p3 * vv.z; acc[3][3] += p3 * vv.w;
    }
#pragma unroll
    for (int ii = 0; ii < 4; ii++)
      *(float4*)(sq + (i0 + ii) * CDIM + h * HDIM + d0) =
          make_float4(acc[ii][0], acc[ii][1], acc[ii][2], acc[ii][3]);
  }
  __syncthreads();

  // scatter ctx rows to voxel order (inverse permutation)
  for (int e = tid; e < SETL * 48; e += 256) {
    int l = e / 48, c4 = e % 48;
    *(float4*)(ctx_out + (size_t)sind[l] * CDIM + c4 * 4) =
        *(const float4*)(sq + l * CDIM + c4 * 4);
  }
}

// ---------------- LayerNorm kernels (warp per row, C=192 -> 6 per lane) ------
__device__ __forceinline__ void warp_red2(float& s, float& s2) {
#pragma unroll
  for (int off = 16; off; off >>= 1) {
    s  += __shfl_xor_sync(0xffffffffu, s,  off);
    s2 += __shfl_xor_sync(0xffffffffu, s2, off);
  }
}

__global__ __launch_bounds__(256)
void ln_add_kernel(const float* __restrict__ a, const float* __restrict__ b,
                   const float* __restrict__ g, const float* __restrict__ be,
                   float* __restrict__ out) {
  int row  = blockIdx.x * 8 + (threadIdx.x >> 5);
  int lane = threadIdx.x & 31;
  const float* ar = a + (size_t)row * CDIM;
  const float* br = b + (size_t)row * CDIM;
  float x[6], s = 0.f, s2 = 0.f;
#pragma unroll
  for (int j = 0; j < 6; j++) {
    int c = lane + j * 32;
    x[j] = ar[c] + br[c];
    s += x[j]; s2 += x[j] * x[j];
  }
  warp_red2(s, s2);
  float mu = s * (1.f / CDIM);
  float rs = rsqrtf(s2 * (1.f / CDIM) - mu * mu + 1e-5f);
#pragma unroll
  for (int j = 0; j < 6; j++) {
    int c = lane + j * 32;
    out[(size_t)row * CDIM + c] = (x[j] - mu) * rs * g[c] + be[c];
  }
}

// out = LN3( LN2(x1 + ffn) + src )
__global__ __launch_bounds__(256)
void ln_final_kernel(const float* __restrict__ x1, const float* __restrict__ ffn,
                     const float* __restrict__ src,
                     const float* __restrict__ g2, const float* __restrict__ b2,
                     const float* __restrict__ g3, const float* __restrict__ b3,
                     float* __restrict__ out) {
  int row  = blockIdx.x * 8 + (threadIdx.x >> 5);
  int lane = threadIdx.x & 31;
  size_t base = (size_t)row * CDIM;
  float x[6], s = 0.f, s2 = 0.f;
#pragma unroll
  for (int j = 0; j < 6; j++) {
    int c = lane + j * 32;
    x[j] = x1[base + c] + ffn[base + c];
    s += x[j]; s2 += x[j] * x[j];
  }
  warp_red2(s, s2);
  float mu = s * (1.f / CDIM);
  float rs = rsqrtf(s2 * (1.f / CDIM) - mu * mu + 1e-5f);
  float z[6]; s = 0.f; s2 = 0.f;
#pragma unroll
  for (int j = 0; j < 6; j++) {
    int c = lane + j * 32;
    z[j] = (x[j] - mu) * rs * g2[c] + b2[c] + src[base + c];
    s += z[j]; s2 += z[j] * z[j];
  }
  warp_red2(s, s2);
  float mu2 = s * (1.f / CDIM);
  float rs2 = rsqrtf(s2 * (1.f / CDIM) - mu2 * mu2 + 1e-5f);
#pragma unroll
  for (int j = 0; j < 6; j++) {
    int c = lane + j * 32;
    out[base + c] = (z[j] - mu2) * rs2 * g3[c] + b3[c];
  }
}

// -------------------------------- launcher -----------------------------------
extern "C" void kernel_launch(void* const* d_in, const int* in_sizes, int n_in,
                              void* d_out, int out_size) {
  const float* src   = (const float*)d_in[0];
  const float* pos   = (const float*)d_in[1];
  const float* w_qkv = (const float*)d_in[2];
  const float* b_qkv = (const float*)d_in[3];
  const float* w_out = (const float*)d_in[4];
  const float* b_out = (const float*)d_in[5];
  const float* w1    = (const float*)d_in[6];
  const float* b1    = (const float*)d_in[7];
  const float* w2    = (const float*)d_in[8];
  const float* b2    = (const float*)d_in[9];
  const float* ln1_g = (const float*)d_in[10];
  const float* ln1_b = (const float*)d_in[11];
  const float* ln2_g = (const float*)d_in[12];
  const float* ln2_b = (const float*)d_in[13];
  const float* ln3_g = (const float*)d_in[14];
  const float* ln3_b = (const float*)d_in[15];
  const int*   vinds = (const int*)d_in[16];
  const unsigned char* kpm = (const unsigned char*)d_in[17];
  float* out = (float*)d_out;

  float *p_qk, *p_v, *p_ctx, *p_src2, *p_x1, *p_h, *p_ffn;
  cudaGetSymbolAddress((void**)&p_qk,   g_qk);
  cudaGetSymbolAddress((void**)&p_v,    g_v);
  cudaGetSymbolAddress((void**)&p_ctx,  g_ctx);
  cudaGetSymbolAddress((void**)&p_src2, g_src2);
  cudaGetSymbolAddress((void**)&p_x1,   g_x1);
  cudaGetSymbolAddress((void**)&p_h,    g_h);
  cudaGetSymbolAddress((void**)&p_ffn,  g_ffn);

  static const int ATTN_SMEM = (3 * SETL * CDIM + NHEAD * SETL * SETL) * 4;  // 184320
  cudaFuncSetAttribute(attn_kernel, cudaFuncAttributeMaxDynamicSharedMemorySize, ATTN_SMEM);

  const int RB = N_VOX / 128;  // 1536 row blocks

  // 1) Q,K = (src+pos) @ Wqk^T + b   (M=384)
  gemm_kernel<true,  false><<<dim3(384 / 64, RB), 128>>>(src, pos, w_qkv, b_qkv, p_qk, CDIM, 384);
  // 2) V = src @ Wv^T + bv           (M=192)
  gemm_kernel<false, false><<<dim3(192 / 64, RB), 128>>>(src, nullptr, w_qkv + 384 * CDIM,
                                                         b_qkv + 384, p_v, CDIM, CDIM);
  // 3) per-set attention + scatter
  attn_kernel<<<SETS, 256, ATTN_SMEM>>>(p_qk, p_v, vinds, kpm, p_ctx);
  // 4) out-proj
  gemm_kernel<false, false><<<dim3(192 / 64, RB), 128>>>(p_ctx, nullptr, w_out, b_out,
                                                         p_src2, CDIM, CDIM);
  // 5) x1 = LN1(src + src2)
  ln_add_kernel<<<N_VOX / 8, 256>>>(src, p_src2, ln1_g, ln1_b, p_x1);
  // 6) h = relu(x1 @ w1^T + b1)      (M=384)
  gemm_kernel<false, true ><<<dim3(384 / 64, RB), 128>>>(p_x1, nullptr, w1, b1, p_h, CDIM, FDIM);
  // 7) ffn = h @ w2^T + b2           (K=384, M=192)
  gemm_kernel<false, false><<<dim3(192 / 64, RB), 128>>>(p_h, nullptr, w2, b2, p_ffn, FDIM, CDIM);
  // 8) out = LN3( LN2(x1 + ffn) + src )
  ln_final_kernel<<<N_VOX / 8, 256>>>(p_x1, p_ffn, src, ln2_g, ln2_b, ln3_g, ln3_b, out);
}

// round 8
// speedup vs baseline: 1.0039x; 1.0039x over previous
#include <cuda_runtime.h>
#include <math.h>

#define N_VOX 196608
#define CDIM 192
#define SETS 4096
#define SETL 48
#define NHEAD 8
#define HDIM 24
#define FDIM 384

// ---------------- scratch (static __device__, allocation-free) ----------------
__device__ float g_qk  [(size_t)N_VOX * 2 * CDIM];  // Q | K packed, 384 per row
__device__ float g_v   [(size_t)N_VOX * CDIM];
__device__ float g_ctx [(size_t)N_VOX * CDIM];
__device__ float g_src2[(size_t)N_VOX * CDIM];
__device__ float g_x1  [(size_t)N_VOX * CDIM];
__device__ float g_h   [(size_t)N_VOX * FDIM];
__device__ float g_ffn [(size_t)N_VOX * CDIM];

// ---------------- generic fp32 GEMM: C = A(N x K) @ W(M x K)^T + bias --------
// BM=128 rows, BN=64 cols, BK=16, 128 threads, 8x8 micro-tile per thread.
template<bool ADD2, bool RELU>
__global__ __launch_bounds__(128)
void gemm_kernel(const float* __restrict__ A, const float* __restrict__ A2,
                 const float* __restrict__ W, const float* __restrict__ bias,
                 float* __restrict__ Cout, int K, int M) {
  __shared__ __align__(16) float As[128][17];
  __shared__ __align__(16) float Bs[16][64];
  const int c0 = blockIdx.x * 64;    // col block (fast dim -> L2 reuse of A rows)
  const int r0 = blockIdx.y * 128;   // row block
  const int tid = threadIdx.x;
  const int cx = tid & 7;            // 0..7  -> 8 output cols
  const int cy = tid >> 3;           // 0..15 -> 8 output rows

  float acc[8][8];
#pragma unroll
  for (int i = 0; i < 8; i++)
#pragma unroll
    for (int j = 0; j < 8; j++) acc[i][j] = 0.f;

  for (int k0 = 0; k0 < K; k0 += 16) {
    // load A tile: 128x16 = 512 float4, 4 per thread (coalesced 64B runs)
#pragma unroll
    for (int t = 0; t < 4; t++) {
      int f = t * 128 + tid;
      int row = f >> 2, cq = f & 3;
      float4 av = *(const float4*)(A + (size_t)(r0 + row) * K + k0 + cq * 4);
      if (ADD2) {
        float4 bv = *(const float4*)(A2 + (size_t)(r0 + row) * K + k0 + cq * 4);
        av.x += bv.x; av.y += bv.y; av.z += bv.z; av.w += bv.w;
      }
      As[row][cq * 4 + 0] = av.x; As[row][cq * 4 + 1] = av.y;
      As[row][cq * 4 + 2] = av.z; As[row][cq * 4 + 3] = av.w;
    }
    // load W tile (transposed into Bs[k][m]): 64x16 = 256 float4, 2 per thread
#pragma unroll
    for (int t = 0; t < 2; t++) {
      int f = t * 128 + tid;
      int m = f >> 2, kq = f & 3;
      float4 wv = *(const float4*)(W + (size_t)(c0 + m) * K + k0 + kq * 4);
      Bs[kq * 4 + 0][m] = wv.x; Bs[kq * 4 + 1][m] = wv.y;
      Bs[kq * 4 + 2][m] = wv.z; Bs[kq * 4 + 3][m] = wv.w;
    }
    __syncthreads();
#pragma unroll
    for (int kk = 0; kk < 16; kk++) {
      float a[8];
#pragma unroll
      for (int ii = 0; ii < 8; ii++) a[ii] = As[cy * 8 + ii][kk];
      float4 bA = *(const float4*)&Bs[kk][cx * 8];
      float4 bB = *(const float4*)&Bs[kk][cx * 8 + 4];
      float b[8] = {bA.x, bA.y, bA.z, bA.w, bB.x, bB.y, bB.z, bB.w};
#pragma unroll
      for (int ii = 0; ii < 8; ii++)
#pragma unroll
        for (int jj = 0; jj < 8; jj++) acc[ii][jj] += a[ii] * b[jj];
    }
    __syncthreads();
  }

  float bb[8];
#pragma unroll
  for (int j = 0; j < 8; j++) bb[j] = bias[c0 + cx * 8 + j];
#pragma unroll
  for (int ii = 0; ii < 8; ii++) {
    size_t base = (size_t)(r0 + cy * 8 + ii) * M + c0 + cx * 8;
    float o[8];
#pragma unroll
    for (int j = 0; j < 8; j++) {
      o[j] = acc[ii][j] + bb[j];
      if (RELU) o[j] = fmaxf(o[j], 0.f);
    }
    *(float4*)(Cout + base)     = make_float4(o[0], o[1], o[2], o[3]);
    *(float4*)(Cout + base + 4) = make_float4(o[4], o[5], o[6], o[7]);
  }
}

// ---------------- per-set attention: gather -> softmax(QK^T)V -> scatter -----
__global__ __launch_bounds__(256)
void attn_kernel(const float* __restrict__ qk, const float* __restrict__ v,
                 const int* __restrict__ inds, const unsigned char* __restrict__ mask,
                 float* __restrict__ ctx_out) {
  extern __shared__ __align__(16) float sm[];
  float* sq = sm;                       // 48*192 (later reused for ctx output)
  float* sk = sq + SETL * CDIM;         // 48*192
  float* sv = sk + SETL * CDIM;         // 48*192
  float* ss = sv + SETL * CDIM;         // 8*48*48 scores
  __shared__ int   sind[SETL];
  __shared__ float smask[SETL];

  const int set = blockIdx.x;
  const int tid = threadIdx.x;
  if (tid < SETL) {
    sind[tid]  = inds[set * SETL + tid];
    smask[tid] = mask[set * SETL + tid] ? -1e9f : 0.f;
  }
  __syncthreads();

  // gather Q,K (packed 384/row) and V (192/row), float4 coalesced
  for (int e = tid; e < SETL * 96; e += 256) {
    int l = e / 96, c4 = e % 96;
    float4 val = *(const float4*)(qk + (size_t)sind[l] * 384 + c4 * 4);
    if (c4 < 48) *(float4*)(sq + l * CDIM + c4 * 4) = val;
    else         *(float4*)(sk + l * CDIM + (c4 - 48) * 4) = val;
  }
  for (int e = tid; e < SETL * 48; e += 256) {
    int l = e / 48, c4 = e % 48;
    *(float4*)(sv + l * CDIM + c4 * 4) =
        *(const float4*)(v + (size_t)sind[l] * CDIM + c4 * 4);
  }
  __syncthreads();

  // scores: per head 48x48, 4x4 register tiles -> 8*12*12 = 1152 tiles
  const float scale = 0.2041241452319315f;  // 1/sqrt(24)
  for (int t = tid; t < 1152; t += 256) {
    int h = t / 144, rem = t % 144;
    int i0 = (rem / 12) * 4, j0 = (rem % 12) * 4;
    float acc[4][4] = {};
#pragma unroll
    for (int d4 = 0; d4 < 6; d4++) {
      float4 qv[4], kv[4];
#pragma unroll
      for (int ii = 0; ii < 4; ii++)
        qv[ii] = *(const float4*)(sq + (i0 + ii) * CDIM + h * HDIM + d4 * 4);
#pragma unroll
      for (int jj = 0; jj < 4; jj++)
        kv[jj] = *(const float4*)(sk + (j0 + jj) * CDIM + h * HDIM + d4 * 4);
#pragma unroll
      for (int ii = 0; ii < 4; ii++)
#pragma unroll
        for (int jj = 0; jj < 4; jj++)
          acc[ii][jj] += qv[ii].x * kv[jj].x + qv[ii].y * kv[jj].y +
                         qv[ii].z * kv[jj].z + qv[ii].w * kv[jj].w;
    }
#pragma unroll
    for (int ii = 0; ii < 4; ii++)
#pragma unroll
      for (int jj = 0; jj < 4; jj++)
        ss[h * 2304 + (i0 + ii) * 48 + j0 + jj] = acc[ii][jj] * scale + smask[j0 + jj];
  }
  __syncthreads();

  // softmax over last dim, one thread per (h, i) row: 384 rows
  for (int r = tid; r < 384; r += 256) {
    float* row = ss + r * 48;
    float mx = row[0];
#pragma unroll
    for (int j = 1; j < 48; j++) mx = fmaxf(mx, row[j]);
    float sum = 0.f;
#pragma unroll
    for (int j = 0; j < 48; j++) { float e = expf(row[j] - mx); row[j] = e; sum += e; }
    float inv = 1.f / sum;
#pragma unroll
    for (int j = 0; j < 48; j++) row[j] *= inv;
  }
  __syncthreads();

  // ctx = P @ V per head, 4x4 tiles over (i, d): 8*12*6 = 576 tiles; write into sq
  for (int t = tid; t < 576; t += 256) {
    int h = t / 72, rem = t % 72;
    int i0 = (rem / 6) * 4, d0 = (rem % 6) * 4;
    float acc[4][4] = {};
    for (int j = 0; j < 48; j++) {
      float4 vv = *(const float4*)(sv + j * CDIM + h * HDIM + d0);
      float p0 = ss[h * 2304 + (i0 + 0) * 48 + j];
      float p1 = ss[h * 2304 + (i0 + 1) * 48 + j];
      float p2 = ss[h * 2304 + (i0 + 2) * 48 + j];
      float p3 = ss[h * 2304 + (i0 + 3) * 48 + j];
      acc[0][0] += p0 * vv.x; acc[0][1] += p0 * vv.y; acc[0][2] += p0 * vv.z; acc[0][3] += p0 * vv.w;
      acc[1][0] += p1 * vv.x; acc[1][1] += p1 * vv.y; acc[1][2] += p1 * vv.z; acc[1][3] += p1 * vv.w;
      acc[2][0] += p2 * vv.x; acc[2][1] += p2 * vv.y; acc[2][2] += p2 * vv.z; acc[2][3] += p2 * vv.w;
      acc[3][0] += p3 * vv.x; acc[3][1] += p3 * vv.y; acc[3][2] += p3 * vv.z; acc[3][3] += p3 * vv.w;
    }
#pragma unroll
    for (int ii = 0; ii < 4; ii++)
      *(float4*)(sq + (i0 + ii) * CDIM + h * HDIM + d0) =
          make_float4(acc[ii][0], acc[ii][1], acc[ii][2], acc[ii][3]);
  }
  __syncthreads();

  // scatter ctx rows to voxel order (inverse permutation)
  for (int e = tid; e < SETL * 48; e += 256) {
    int l = e / 48, c4 = e % 48;
    *(float4*)(ctx_out + (size_t)sind[l] * CDIM + c4 * 4) =
        *(const float4*)(sq + l * CDIM + c4 * 4);
  }
}

// ---------------- LayerNorm kernels (warp per row, C=192 -> 6 per lane) ------
__device__ __forceinline__ void warp_red2(float& s, float& s2) {
#pragma unroll
  for (int off = 16; off; off >>= 1) {
    s  += __shfl_xor_sync(0xffffffffu, s,  off);
    s2 += __shfl_xor_sync(0xffffffffu, s2, off);
  }
}

__global__ __launch_bounds__(256)
void ln_add_kernel(const float* __restrict__ a, const float* __restrict__ b,
                   const float* __restrict__ g, const float* __restrict__ be,
                   float* __restrict__ out) {
  int row  = blockIdx.x * 8 + (threadIdx.x >> 5);
  int lane = threadIdx.x & 31;
  const float* ar = a + (size_t)row * CDIM;
  const float* br = b + (size_t)row * CDIM;
  float x[6], s = 0.f, s2 = 0.f;
#pragma unroll
  for (int j = 0; j < 6; j++) {
    int c = lane + j * 32;
    x[j] = ar[c] + br[c];
    s += x[j]; s2 += x[j] * x[j];
  }
  warp_red2(s, s2);
  float mu = s * (1.f / CDIM);
  float rs = rsqrtf(s2 * (1.f / CDIM) - mu * mu + 1e-5f);
#pragma unroll
  for (int j = 0; j < 6; j++) {
    int c = lane + j * 32;
    out[(size_t)row * CDIM + c] = (x[j] - mu) * rs * g[c] + be[c];
  }
}

// out = LN3( LN2(x1 + ffn) + src )
__global__ __launch_bounds__(256)
void ln_final_kernel(const float* __restrict__ x1, const float* __restrict__ ffn,
                     const float* __restrict__ src,
                     const float* __restrict__ g2, const float* __restrict__ b2,
                     const float* __restrict__ g3, const float* __restrict__ b3,
                     float* __restrict__ out) {
  int row  = blockIdx.x * 8 + (threadIdx.x >> 5);
  int lane = threadIdx.x & 31;
  size_t base = (size_t)row * CDIM;
  float x[6], s = 0.f, s2 = 0.f;
#pragma unroll
  for (int j = 0; j < 6; j++) {
    int c = lane + j * 32;
    x[j] = x1[base + c] + ffn[base + c];
    s += x[j]; s2 += x[j] * x[j];
  }
  warp_red2(s, s2);
  float mu = s * (1.f / CDIM);
  float rs = rsqrtf(s2 * (1.f / CDIM) - mu * mu + 1e-5f);
  float z[6]; s = 0.f; s2 = 0.f;
#pragma unroll
  for (int j = 0; j < 6; j++) {
    int c = lane + j * 32;
    z[j] = (x[j] - mu) * rs * g2[c] + b2[c] + src[base + c];
    s += z[j]; s2 += z[j] * z[j];
  }
  warp_red2(s, s2);
  float mu2 = s * (1.f / CDIM);
  float rs2 = rsqrtf(s2 * (1.f / CDIM) - mu2 * mu2 + 1e-5f);
#pragma unroll
  for (int j = 0; j < 6; j++) {
    int c = lane + j * 32;
    out[base + c] = (z[j] - mu2) * rs2 * g3[c] + b3[c];
  }
}

// -------------------------------- launcher -----------------------------------
extern "C" void kernel_launch(void* const* d_in, const int* in_sizes, int n_in,
                              void* d_out, int out_size) {
  const float* src   = (const float*)d_in[0];
  const float* pos   = (const float*)d_in[1];
  const float* w_qkv = (const float*)d_in[2];
  const float* b_qkv = (const float*)d_in[3];
  const float* w_out = (const float*)d_in[4];
  const float* b_out = (const float*)d_in[5];
  const float* w1    = (const float*)d_in[6];
  const float* b1    = (const float*)d_in[7];
  const float* w2    = (const float*)d_in[8];
  const float* b2    = (const float*)d_in[9];
  const float* ln1_g = (const float*)d_in[10];
  const float* ln1_b = (const float*)d_in[11];
  const float* ln2_g = (const float*)d_in[12];
  const float* ln2_b = (const float*)d_in[13];
  const float* ln3_g = (const float*)d_in[14];
  const float* ln3_b = (const float*)d_in[15];
  const int*   vinds = (const int*)d_in[16];
  const unsigned char* kpm = (const unsigned char*)d_in[17];
  float* out = (float*)d_out;

  float *p_qk, *p_v, *p_ctx, *p_src2, *p_x1, *p_h, *p_ffn;
  cudaGetSymbolAddress((void**)&p_qk,   g_qk);
  cudaGetSymbolAddress((void**)&p_v,    g_v);
  cudaGetSymbolAddress((void**)&p_ctx,  g_ctx);
  cudaGetSymbolAddress((void**)&p_src2, g_src2);
  cudaGetSymbolAddress((void**)&p_x1,   g_x1);
  cudaGetSymbolAddress((void**)&p_h,    g_h);
  cudaGetSymbolAddress((void**)&p_ffn,  g_ffn);

  static const int ATTN_SMEM = (3 * SETL * CDIM + NHEAD * SETL * SETL) * 4;  // 184320
  cudaFuncSetAttribute(attn_kernel, cudaFuncAttributeMaxDynamicSharedMemorySize, ATTN_SMEM);

  const int RB = N_VOX / 128;  // 1536 row blocks

  // 1) Q,K = (src+pos) @ Wqk^T + b   (M=384)
  gemm_kernel<true,  false><<<dim3(384 / 64, RB), 128>>>(src, pos, w_qkv, b_qkv, p_qk, CDIM, 384);
  // 2) V = src @ Wv^T + bv           (M=192)
  gemm_kernel<false, false><<<dim3(192 / 64, RB), 128>>>(src, nullptr, w_qkv + 384 * CDIM,
                                                         b_qkv + 384, p_v, CDIM, CDIM);
  // 3) per-set attention + scatter
  attn_kernel<<<SETS, 256, ATTN_SMEM>>>(p_qk, p_v, vinds, kpm, p_ctx);
  // 4) out-proj
  gemm_kernel<false, false><<<dim3(192 / 64, RB), 128>>>(p_ctx, nullptr, w_out, b_out,
                                                         p_src2, CDIM, CDIM);
  // 5) x1 = LN1(src + src2)
  ln_add_kernel<<<N_VOX / 8, 256>>>(src, p_src2, ln1_g, ln1_b, p_x1);
  // 6) h = relu(x1 @ w1^T + b1)      (M=384)
  gemm_kernel<false, true ><<<dim3(384 / 64, RB), 128>>>(p_x1, nullptr, w1, b1, p_h, CDIM, FDIM);
  // 7) ffn = h @ w2^T + b2           (K=384, M=192)
  gemm_kernel<false, false><<<dim3(192 / 64, RB), 128>>>(p_h, nullptr, w2, b2, p_ffn, FDIM, CDIM);
  // 8) out = LN3( LN2(x1 + ffn) + src )
  ln_final_kernel<<<N_VOX / 8, 256>>>(p_x1, p_ffn, src, ln2_g, ln2_b, ln3_g, ln3_b, out);
}